// round 5
// baseline (speedup 1.0000x reference)
#include <cuda_runtime.h>
#include <math.h>

#define IN_SIZE  256
#define N_NODES  512
#define OUT_SIZE 64
#define TT       2048
#define DD       832          // IN_SIZE + N_NODES + OUT_SIZE
#define FAN_IN   32
#define GD       768          // IN_SIZE + N_NODES (gather index range)
#define MAXE     (N_NODES * FAN_IN)

// ---------------- device scratch (no allocations allowed) ----------------
__device__ float  g_actT[GD * TT];       // actT[d][t] = actives[t+1][d], t in [0,2047)
__device__ float  g_K[N_NODES * TT];     // K[ix][t] for t<2047 (slot 2047 zeroed)
__device__ float  g_V[N_NODES * TT];
__device__ float  g_kmax[N_NODES];
__device__ float  g_kmin[N_NODES];
__device__ float  g_stat[N_NODES * 3];   // static (x-part) of q,k,v per node
__device__ float  g_immA[N_NODES * 3];   // coeff for out_{ix-1}
__device__ float  g_immB[N_NODES * 3];   // coeff for out_{ix-2}
__device__ int    g_cnt[N_NODES];        // scatter edges per source
__device__ int    g_off[N_NODES + 1];    // CSR offsets
__device__ int    g_fill[N_NODES];       // fill cursors
__device__ float4 g_edge[MAXE];          // {w0,w1,w2, target-as-bits}, grouped by source

// ---------------- Phase A: tiled shifted transpose ----------------
__global__ void transpose_kernel(const float* __restrict__ actives) {
    __shared__ float tile[32][33];
    int d0 = blockIdx.x * 32;
    int t0 = blockIdx.y * 32;
    int tx = threadIdx.x, ty = threadIdx.y;        // 32 x 8
    #pragma unroll
    for (int r = 0; r < 32; r += 8) {
        int t = t0 + ty + r;
        if (t < TT - 1) tile[ty + r][tx] = actives[(t + 1) * DD + d0 + tx];
    }
    __syncthreads();
    #pragma unroll
    for (int r = 0; r < 32; r += 8) {
        int t = t0 + tx;
        if (t < TT - 1) g_actT[(d0 + ty + r) * TT + t] = tile[tx][ty + r];
    }
}

// ---------------- Phase B: per-node K/V precompute + kmin/kmax ----------------
__global__ void __launch_bounds__(256) precompute_kernel(
    const float* __restrict__ weights, const int* __restrict__ in_idxs) {
    int ix  = blockIdx.x;
    int tid = threadIdx.x;
    __shared__ int   s_idx[FAN_IN];
    __shared__ float s_w1[FAN_IN], s_w2[FAN_IN];
    __shared__ float s_red[16];

    if (tid < FAN_IN) {
        s_idx[tid] = in_idxs[ix * FAN_IN + tid];
        s_w1[tid]  = weights[(ix * FAN_IN + tid) * 3 + 1];
        s_w2[tid]  = weights[(ix * FAN_IN + tid) * 3 + 2];
    }
    __syncthreads();

    float kmax = -INFINITY, kmin = INFINITY;
    for (int t = tid; t < TT; t += 256) {
        if (t < TT - 1) {
            float k = 0.f, v = 0.f;
            #pragma unroll
            for (int j = 0; j < FAN_IN; j++) {
                float a = g_actT[s_idx[j] * TT + t];
                k += a * s_w1[j];
                v += a * s_w2[j];
            }
            g_K[ix * TT + t] = k;
            g_V[ix * TT + t] = v;
            kmax = fmaxf(kmax, k);
            kmin = fminf(kmin, k);
        } else {
            g_K[ix * TT + t] = 0.f;
            g_V[ix * TT + t] = 0.f;
        }
    }
    #pragma unroll
    for (int o = 16; o > 0; o >>= 1) {
        kmax = fmaxf(kmax, __shfl_xor_sync(0xFFFFFFFFu, kmax, o));
        kmin = fminf(kmin, __shfl_xor_sync(0xFFFFFFFFu, kmin, o));
    }
    int w = tid >> 5;
    if ((tid & 31) == 0) { s_red[w] = kmax; s_red[8 + w] = kmin; }
    __syncthreads();
    if (tid == 0) {
        float mx = s_red[0], mn = s_red[8];
        #pragma unroll
        for (int i = 1; i < 8; i++) { mx = fmaxf(mx, s_red[i]); mn = fminf(mn, s_red[8 + i]); }
        g_kmax[ix] = mx;
        g_kmin[ix] = mn;
    }
}

// ---------------- scatter-graph construction ----------------
__global__ void zero_kernel() {
    int i = blockIdx.x * blockDim.x + threadIdx.x;
    if (i < N_NODES) g_cnt[i] = 0;
}

__global__ void build_static(const float* __restrict__ x,
                             const float* __restrict__ weights,
                             const int* __restrict__ in_idxs) {
    int ix = blockIdx.x * blockDim.x + threadIdx.x;
    if (ix >= N_NODES) return;
    float s0=0,s1=0,s2=0, a0=0,a1=0,a2=0, b0=0,b1=0,b2=0;
    #pragma unroll 4
    for (int j = 0; j < FAN_IN; j++) {
        int   idx = in_idxs[ix * FAN_IN + j];
        float w0  = weights[(ix * FAN_IN + j) * 3 + 0];
        float w1  = weights[(ix * FAN_IN + j) * 3 + 1];
        float w2  = weights[(ix * FAN_IN + j) * 3 + 2];
        if (idx < IN_SIZE) {
            float xv = x[idx];
            s0 += w0 * xv; s1 += w1 * xv; s2 += w2 * xv;
        } else {
            int m = idx - IN_SIZE;
            if      (m == ix - 1) { a0 += w0; a1 += w1; a2 += w2; }
            else if (m == ix - 2) { b0 += w0; b1 += w1; b2 += w2; }
            else if (m <= ix - 3) atomicAdd(&g_cnt[m], 1);
            // m >= ix: row entry is still zero when node ix executes -> drop
        }
    }
    g_stat[ix*3+0]=s0; g_stat[ix*3+1]=s1; g_stat[ix*3+2]=s2;
    g_immA[ix*3+0]=a0; g_immA[ix*3+1]=a1; g_immA[ix*3+2]=a2;
    g_immB[ix*3+0]=b0; g_immB[ix*3+1]=b1; g_immB[ix*3+2]=b2;
}

__global__ void __launch_bounds__(N_NODES) prefix_kernel() {
    __shared__ int sc[N_NODES];
    int tid = threadIdx.x;
    int v = g_cnt[tid];
    sc[tid] = v;
    __syncthreads();
    #pragma unroll
    for (int o = 1; o < N_NODES; o <<= 1) {
        int t = (tid >= o) ? sc[tid - o] : 0;
        __syncthreads();
        sc[tid] += t;
        __syncthreads();
    }
    g_off[tid + 1] = sc[tid];
    g_fill[tid]    = sc[tid] - v;   // exclusive offset
    if (tid == 0) g_off[0] = 0;
}

__global__ void fill_kernel(const float* __restrict__ weights,
                            const int* __restrict__ in_idxs) {
    int ix = blockIdx.x * blockDim.x + threadIdx.x;
    if (ix >= N_NODES) return;
    #pragma unroll 4
    for (int j = 0; j < FAN_IN; j++) {
        int idx = in_idxs[ix * FAN_IN + j];
        if (idx >= IN_SIZE) {
            int m = idx - IN_SIZE;
            if (m <= ix - 3) {
                float w0 = weights[(ix * FAN_IN + j) * 3 + 0];
                float w1 = weights[(ix * FAN_IN + j) * 3 + 1];
                float w2 = weights[(ix * FAN_IN + j) * 3 + 2];
                int pos = atomicAdd(&g_fill[m], 1);
                g_edge[pos] = make_float4(w0, w1, w2, __int_as_float(ix));
            }
        }
    }
}

// ---------------- Phase C: sequential scan, single persistent block ----------------
__global__ void __launch_bounds__(256) seq_kernel(float* __restrict__ out) {
    __shared__ float  s_qa[N_NODES], s_ka[N_NODES], s_va[N_NODES];
    __shared__ float2 s_p[2][8];

    int tid  = threadIdx.x;
    int lane = tid & 31;
    int warp = tid >> 5;

    for (int i = tid; i < N_NODES; i += 256) {
        s_qa[i] = g_stat[i*3+0];
        s_ka[i] = g_stat[i*3+1];
        s_va[i] = g_stat[i*3+2];
    }
    __syncthreads();

    // ---- prime node 0 ----
    float qa_c = s_qa[0], ka_c = s_ka[0], va_c = s_va[0];
    float iA0 = g_immA[0], iA1 = g_immA[1], iA2 = g_immA[2];
    float iB0 = g_immB[0], iB1 = g_immB[1], iB2 = g_immB[2];
    float kmx = g_kmax[0], kmn = g_kmin[0];
    float4 k0 = *(const float4*)&g_K[tid * 8];
    float4 k1 = *(const float4*)&g_K[tid * 8 + 4];
    float4 v0 = *(const float4*)&g_V[tid * 8];
    float4 v1 = *(const float4*)&g_V[tid * 8 + 4];
    // edge state: loaded by the prefetch of step ix for use by step ix+1's
    // scatter (scatter at step s pushes out_{s-1}, i.e. source s-1's edges,
    // which are loaded during step s-1). Step 0 never scatters.
    int   e_off = 0;
    int   e_cnt = 0;
    float4 epf = make_float4(0.f, 0.f, 0.f, __int_as_float(0));

    float out1 = 0.f, out2 = 0.f;

    for (int ix = 0; ix < N_NODES; ix++) {
        // q/kl/vl: accumulated base + immediate terms (no gather, no reduction)
        float q  = fmaf(iA0, out1, fmaf(iB0, out2, qa_c));
        float kl = fmaf(iA1, out1, fmaf(iB1, out2, ka_c));
        float vl = fmaf(iA2, out1, fmaf(iB2, out2, va_c));
        float maxl = fmaxf((q >= 0.f) ? q * kmx : q * kmn, q * kl);

        // scatter out1 (source ix-1) into future accumulators (targets >= ix+2)
        if (ix > 0) {
            if (tid < e_cnt) {
                int tgt = __float_as_int(epf.w);
                atomicAdd(&s_qa[tgt], epf.x * out1);
                atomicAdd(&s_ka[tgt], epf.y * out1);
                atomicAdd(&s_va[tgt], epf.z * out1);
            }
            for (int e = 256 + tid; e < e_cnt; e += 256) {   // rare overflow wave
                float4 ed = g_edge[e_off + e];
                int tgt = __float_as_int(ed.w);
                atomicAdd(&s_qa[tgt], ed.x * out1);
                atomicAdd(&s_ka[tgt], ed.y * out1);
                atomicAdd(&s_va[tgt], ed.z * out1);
            }
        }

        // snapshot current K/V before prefetch overwrites
        float kk[8] = {k0.x,k0.y,k0.z,k0.w,k1.x,k1.y,k1.z,k1.w};
        float vv[8] = {v0.x,v0.y,v0.z,v0.w,v1.x,v1.y,v1.z,v1.w};

        // prefetch node ix+1 state + SOURCE-ix edges (for step ix+1's scatter)
        if (ix + 1 < N_NODES) {
            int b = ix + 1;
            qa_c = s_qa[b]; ka_c = s_ka[b]; va_c = s_va[b];   // final since step ix-1
            iA0 = g_immA[b*3]; iA1 = g_immA[b*3+1]; iA2 = g_immA[b*3+2];
            iB0 = g_immB[b*3]; iB1 = g_immB[b*3+1]; iB2 = g_immB[b*3+2];
            kmx = g_kmax[b]; kmn = g_kmin[b];
            k0 = *(const float4*)&g_K[b * TT + tid * 8];
            k1 = *(const float4*)&g_K[b * TT + tid * 8 + 4];
            v0 = *(const float4*)&g_V[b * TT + tid * 8];
            v1 = *(const float4*)&g_V[b * TT + tid * 8 + 4];
            e_off = g_off[ix];                     // edges of SOURCE ix
            e_cnt = g_off[ix + 1] - e_off;
            epf = (tid < e_cnt) ? g_edge[e_off + tid]
                                : make_float4(0.f, 0.f, 0.f, __int_as_float(0));
        }

        // 8 exps per thread (elem 2047 excluded on thread 255 only)
        float se = 0.f, sev = 0.f;
        #pragma unroll
        for (int i = 0; i < 7; i++) {
            float e = __expf(fmaf(q, kk[i], -maxl));
            se += e; sev = fmaf(e, vv[i], sev);
        }
        {
            float e7 = __expf(fmaf(q, kk[7], -maxl));
            if (tid != 255) { se += e7; sev = fmaf(e7, vv[7], sev); }
        }

        // live t=2047 term (off the reduction path)
        float tse  = __expf(fmaf(q, kl, -maxl));
        float tsev = tse * vl;

        #pragma unroll
        for (int o = 16; o > 0; o >>= 1) {
            se  += __shfl_xor_sync(0xFFFFFFFFu, se,  o);
            sev += __shfl_xor_sync(0xFFFFFFFFu, sev, o);
        }
        int pb = ix & 1;
        if (lane == 0) s_p[pb][warp] = make_float2(se, sev);
        __syncthreads();   // the ONLY bar per node; also orders the scatter

        float fse = tse, fsev = tsev;
        #pragma unroll
        for (int i = 0; i < 8; i++) { float2 p = s_p[pb][i]; fse += p.x; fsev += p.y; }

        float r  = __fdividef(fsev, fse);
        float y  = __expf(2.f * r);
        float ov = 1.f - __fdividef(2.f, y + 1.f);   // tanh(r), robust at +/-inf
        out2 = out1;
        out1 = ov;

        if (tid == 0 && ix >= N_NODES - OUT_SIZE)
            out[ix - (N_NODES - OUT_SIZE)] = ov;
    }
}

// ---------------- launch ----------------
extern "C" void kernel_launch(void* const* d_in, const int* in_sizes, int n_in,
                              void* d_out, int out_size) {
    const float* x       = (const float*)d_in[0];
    const float* actives = (const float*)d_in[1];
    const float* weights = (const float*)d_in[2];
    const int*   in_idxs = (const int*)  d_in[3];
    float* out = (float*)d_out;

    transpose_kernel<<<dim3(GD / 32, (TT + 30) / 32), dim3(32, 8)>>>(actives);
    zero_kernel<<<2, 256>>>();
    build_static<<<2, 256>>>(x, weights, in_idxs);
    prefix_kernel<<<1, N_NODES>>>();
    fill_kernel<<<2, 256>>>(weights, in_idxs);
    precompute_kernel<<<N_NODES, 256>>>(weights, in_idxs);
    seq_kernel<<<1, 256>>>(out);
}

// round 6
// speedup vs baseline: 1.1438x; 1.1438x over previous
#include <cuda_runtime.h>
#include <math.h>

#define IN_SIZE  256
#define N_NODES  512
#define OUT_SIZE 64
#define TT       2048
#define DD       832
#define FAN_IN   32
#define GD       768
#define MAXE     (N_NODES * FAN_IN)
#define LOG2E    1.4426950408889634f

// ---------------- device scratch ----------------
__device__ float  g_actT[GD * TT];
__device__ float  g_K[N_NODES * TT];     // K*log2e, slot 2047 zeroed
__device__ float  g_V[N_NODES * TT];
__device__ float  g_kmax[N_NODES];       // on scaled K
__device__ float  g_kmin[N_NODES];
__device__ float  g_stat[N_NODES * 3];   // q,k2,v static parts (k scaled by log2e)
__device__ float  g_immA[N_NODES * 3];
__device__ float  g_immB[N_NODES * 3];
__device__ int    g_off[N_NODES + 1];
__device__ float4 g_edge[MAXE];          // {w0, w1*log2e, w2, target-bits}

__device__ __forceinline__ float ex2f(float x) {
    float r; asm("ex2.approx.ftz.f32 %0, %1;" : "=f"(r) : "f"(x)); return r;
}

// ---------------- Phase A: tiled shifted transpose ----------------
__global__ void transpose_kernel(const float* __restrict__ actives) {
    __shared__ float tile[32][33];
    int d0 = blockIdx.x * 32;
    int t0 = blockIdx.y * 32;
    int tx = threadIdx.x, ty = threadIdx.y;        // 32 x 8
    #pragma unroll
    for (int r = 0; r < 32; r += 8) {
        int t = t0 + ty + r;
        if (t < TT - 1) tile[ty + r][tx] = actives[(t + 1) * DD + d0 + tx];
    }
    __syncthreads();
    #pragma unroll
    for (int r = 0; r < 32; r += 8) {
        int t = t0 + tx;
        if (t < TT - 1) g_actT[(d0 + ty + r) * TT + t] = tile[tx][ty + r];
    }
}

// ---------------- Phase B: K/V precompute (K scaled by log2e) ----------------
__global__ void __launch_bounds__(256) precompute_kernel(
    const float* __restrict__ weights, const int* __restrict__ in_idxs) {
    int ix  = blockIdx.x;
    int tid = threadIdx.x;
    __shared__ int   s_idx[FAN_IN];
    __shared__ float s_w1[FAN_IN], s_w2[FAN_IN];
    __shared__ float s_red[16];

    if (tid < FAN_IN) {
        s_idx[tid] = in_idxs[ix * FAN_IN + tid];
        s_w1[tid]  = weights[(ix * FAN_IN + tid) * 3 + 1] * LOG2E;
        s_w2[tid]  = weights[(ix * FAN_IN + tid) * 3 + 2];
    }
    __syncthreads();

    float kmax = -INFINITY, kmin = INFINITY;
    for (int t = tid; t < TT; t += 256) {
        if (t < TT - 1) {
            float k = 0.f, v = 0.f;
            #pragma unroll
            for (int j = 0; j < FAN_IN; j++) {
                float a = g_actT[s_idx[j] * TT + t];
                k += a * s_w1[j];
                v += a * s_w2[j];
            }
            g_K[ix * TT + t] = k;
            g_V[ix * TT + t] = v;
            kmax = fmaxf(kmax, k);
            kmin = fminf(kmin, k);
        } else {
            g_K[ix * TT + t] = 0.f;
            g_V[ix * TT + t] = 0.f;
        }
    }
    #pragma unroll
    for (int o = 16; o > 0; o >>= 1) {
        kmax = fmaxf(kmax, __shfl_xor_sync(0xFFFFFFFFu, kmax, o));
        kmin = fminf(kmin, __shfl_xor_sync(0xFFFFFFFFu, kmin, o));
    }
    int w = tid >> 5;
    if ((tid & 31) == 0) { s_red[w] = kmax; s_red[8 + w] = kmin; }
    __syncthreads();
    if (tid == 0) {
        float mx = s_red[0], mn = s_red[8];
        #pragma unroll
        for (int i = 1; i < 8; i++) { mx = fmaxf(mx, s_red[i]); mn = fminf(mn, s_red[8 + i]); }
        g_kmax[ix] = mx;
        g_kmin[ix] = mn;
    }
}

// ---------------- fused graph construction (one block, 512 threads) ----------------
__global__ void __launch_bounds__(N_NODES) graph_kernel(
    const float* __restrict__ x,
    const float* __restrict__ weights,
    const int* __restrict__ in_idxs) {
    __shared__ int s_cnt[N_NODES];
    __shared__ int s_fill[N_NODES];
    int ix = threadIdx.x;
    s_cnt[ix] = 0;
    __syncthreads();

    float s0=0,s1=0,s2=0, a0=0,a1=0,a2=0, b0=0,b1=0,b2=0;
    #pragma unroll 4
    for (int j = 0; j < FAN_IN; j++) {
        int   idx = in_idxs[ix * FAN_IN + j];
        float w0  = weights[(ix * FAN_IN + j) * 3 + 0];
        float w1  = weights[(ix * FAN_IN + j) * 3 + 1] * LOG2E;
        float w2  = weights[(ix * FAN_IN + j) * 3 + 2];
        if (idx < IN_SIZE) {
            float xv = x[idx];
            s0 += w0 * xv; s1 += w1 * xv; s2 += w2 * xv;
        } else {
            int m = idx - IN_SIZE;
            if      (m == ix - 1) { a0 += w0; a1 += w1; a2 += w2; }
            else if (m == ix - 2) { b0 += w0; b1 += w1; b2 += w2; }
            else if (m <= ix - 3) atomicAdd(&s_cnt[m], 1);
        }
    }
    g_stat[ix*3+0]=s0; g_stat[ix*3+1]=s1; g_stat[ix*3+2]=s2;
    g_immA[ix*3+0]=a0; g_immA[ix*3+1]=a1; g_immA[ix*3+2]=a2;
    g_immB[ix*3+0]=b0; g_immB[ix*3+1]=b1; g_immB[ix*3+2]=b2;
    __syncthreads();

    int v = s_cnt[ix];
    #pragma unroll
    for (int o = 1; o < N_NODES; o <<= 1) {
        int t = (ix >= o) ? s_cnt[ix - o] : 0;
        __syncthreads();
        s_cnt[ix] += t;
        __syncthreads();
    }
    int incl = s_cnt[ix];
    g_off[ix + 1] = incl;
    if (ix == 0) g_off[0] = 0;
    s_fill[ix] = incl - v;
    __syncthreads();

    #pragma unroll 4
    for (int j = 0; j < FAN_IN; j++) {
        int idx = in_idxs[ix * FAN_IN + j];
        if (idx >= IN_SIZE) {
            int m = idx - IN_SIZE;
            if (m <= ix - 3) {
                float w0 = weights[(ix * FAN_IN + j) * 3 + 0];
                float w1 = weights[(ix * FAN_IN + j) * 3 + 1] * LOG2E;
                float w2 = weights[(ix * FAN_IN + j) * 3 + 2];
                int pos = atomicAdd(&s_fill[m], 1);
                g_edge[pos] = make_float4(w0, w1, w2, __int_as_float(ix));
            }
        }
    }
}

// ---------------- Phase C: sequential scan ----------------
__global__ void __launch_bounds__(256) seq_kernel(float* __restrict__ out) {
    __shared__ float  s_qa[N_NODES], s_ka[N_NODES], s_va[N_NODES];
    __shared__ float4 s_i4[N_NODES];     // iA0,iA1,iA2,iB0
    __shared__ float2 s_i2[N_NODES];     // iB1,iB2
    __shared__ float2 s_mm[N_NODES];     // kmax,kmin (scaled)
    __shared__ int    s_off[N_NODES + 1];
    __shared__ float2 s_p[2][8];

    int tid  = threadIdx.x;
    int lane = tid & 31;
    int warp = tid >> 5;

    for (int i = tid; i < N_NODES; i += 256) {
        s_qa[i] = g_stat[i*3+0];
        s_ka[i] = g_stat[i*3+1];
        s_va[i] = g_stat[i*3+2];
        s_i4[i] = make_float4(g_immA[i*3+0], g_immA[i*3+1], g_immA[i*3+2], g_immB[i*3+0]);
        s_i2[i] = make_float2(g_immB[i*3+1], g_immB[i*3+2]);
        s_mm[i] = make_float2(g_kmax[i], g_kmin[i]);
        s_off[i] = g_off[i];
    }
    if (tid == 0) s_off[N_NODES] = g_off[N_NODES];
    __syncthreads();

    // ---- prime node 0 ----
    float qa_c = s_qa[0], ka_c = s_ka[0], va_c = s_va[0];
    float4 i4 = s_i4[0];
    float2 i2 = s_i2[0];
    float2 mm = s_mm[0];
    float4 k0 = *(const float4*)&g_K[tid * 8];
    float4 k1 = *(const float4*)&g_K[tid * 8 + 4];
    float4 v0 = *(const float4*)&g_V[tid * 8];
    float4 v1 = *(const float4*)&g_V[tid * 8 + 4];
    // edge double-buffer: cur used by this step's scatter (source ix-1),
    // nxt loaded this step (source ix) for next step's scatter.
    int    ecnt_c = 0, eoff_c = 0;
    float4 ep_c = make_float4(0.f, 0.f, 0.f, __int_as_float(0));

    float out1 = 0.f, out2 = 0.f;

    for (int ix = 0; ix < N_NODES; ix++) {
        // ---- critical: q / kl2 / vl from registers only ----
        float q   = fmaf(i4.x, out1, fmaf(i4.w, out2, qa_c));
        float kl2 = fmaf(i4.y, out1, fmaf(i2.x, out2, ka_c));
        float vl  = fmaf(i4.z, out1, fmaf(i2.y, out2, va_c));
        float maxl = fmaxf(fmaxf(q * mm.x, q * mm.y), q * kl2);

        // snapshot K/V before prefetch overwrites
        float kk[8] = {k0.x,k0.y,k0.z,k0.w,k1.x,k1.y,k1.z,k1.w};
        float vv[8] = {v0.x,v0.y,v0.z,v0.w,v1.x,v1.y,v1.z,v1.w};

        // ---- prefetch node ix+1 (scalars via LDS, K/V + edges via LDG) ----
        int    ecnt_n = 0, eoff_n = 0;
        float4 ep_n = make_float4(0.f, 0.f, 0.f, __int_as_float(0));
        if (ix + 1 < N_NODES) {
            int b = ix + 1;
            qa_c = s_qa[b]; ka_c = s_ka[b]; va_c = s_va[b];
            i4 = s_i4[b]; i2 = s_i2[b]; mm = s_mm[b];
            k0 = *(const float4*)&g_K[b * TT + tid * 8];
            k1 = *(const float4*)&g_K[b * TT + tid * 8 + 4];
            v0 = *(const float4*)&g_V[b * TT + tid * 8];
            v1 = *(const float4*)&g_V[b * TT + tid * 8 + 4];
            eoff_n = s_off[ix];                      // edges of SOURCE ix
            ecnt_n = s_off[ix + 1] - eoff_n;
            if (tid < ecnt_n) ep_n = g_edge[eoff_n + tid];
        }

        // ---- 8 exps/thread (bare ex2, K pre-scaled by log2e) ----
        float se = 0.f, sev = 0.f;
        #pragma unroll
        for (int i = 0; i < 7; i++) {
            float e = ex2f(fmaf(q, kk[i], -maxl));
            se += e; sev = fmaf(e, vv[i], sev);
        }
        {
            float e7 = ex2f(fmaf(q, kk[7], -maxl));
            if (tid != 255) { se += e7; sev = fmaf(e7, vv[7], sev); }
        }
        float tse  = ex2f(fmaf(q, kl2, -maxl));
        float tsev = tse * vl;

        // ---- scatter out1 (source ix-1), loaded LAST step -> full-step slack ----
        if (tid < ecnt_c) {
            int tgt = __float_as_int(ep_c.w);
            atomicAdd(&s_qa[tgt], ep_c.x * out1);
            atomicAdd(&s_ka[tgt], ep_c.y * out1);
            atomicAdd(&s_va[tgt], ep_c.z * out1);
        }
        for (int e = 256 + tid; e < ecnt_c; e += 256) {   // statistically never taken
            float4 ed = g_edge[eoff_c + e];
            int tgt = __float_as_int(ed.w);
            atomicAdd(&s_qa[tgt], ed.x * out1);
            atomicAdd(&s_ka[tgt], ed.y * out1);
            atomicAdd(&s_va[tgt], ed.z * out1);
        }
        ep_c = ep_n; ecnt_c = ecnt_n; eoff_c = eoff_n;

        // ---- reduce ----
        #pragma unroll
        for (int o = 16; o > 0; o >>= 1) {
            se  += __shfl_xor_sync(0xFFFFFFFFu, se,  o);
            sev += __shfl_xor_sync(0xFFFFFFFFu, sev, o);
        }
        int pb = ix & 1;
        if (lane == 0) s_p[pb][warp] = make_float2(se, sev);
        __syncthreads();   // the ONLY bar; also orders the scatter for future prefetch reads

        float fse = tse, fsev = tsev;
        #pragma unroll
        for (int i = 0; i < 8; i++) { float2 p = s_p[pb][i]; fse += p.x; fsev += p.y; }

        float r  = __fdividef(fsev, fse);
        float y  = ex2f(r * (2.f * LOG2E));
        float ov = 1.f - __fdividef(2.f, y + 1.f);   // tanh(r), robust at +/-inf
        out2 = out1;
        out1 = ov;

        if (tid == 0 && ix >= N_NODES - OUT_SIZE)
            out[ix - (N_NODES - OUT_SIZE)] = ov;
    }
}

// ---------------- launch ----------------
extern "C" void kernel_launch(void* const* d_in, const int* in_sizes, int n_in,
                              void* d_out, int out_size) {
    const float* x       = (const float*)d_in[0];
    const float* actives = (const float*)d_in[1];
    const float* weights = (const float*)d_in[2];
    const int*   in_idxs = (const int*)  d_in[3];
    float* out = (float*)d_out;

    transpose_kernel<<<dim3(GD / 32, TT / 32), dim3(32, 8)>>>(actives);
    graph_kernel<<<1, N_NODES>>>(x, weights, in_idxs);
    precompute_kernel<<<N_NODES, 256>>>(weights, in_idxs);
    seq_kernel<<<1, 256>>>(out);
}